// round 15
// baseline (speedup 1.0000x reference)
#include <cuda_runtime.h>
#include <cuda_fp16.h>
#include <cstdint>
#include <math.h>

#define BATCH   131072
#define DIM     256
#define KTOT    1024
#define NOUT    32
#define MTILE   128      // rows per block
#define NCHUNK  16
#define BCHUNK  8192     // B-fragment bytes per chunk: 4ks x 4nt x 32lane x 16B
#define NBUF    4        // B smem buffers; prefetch distance 2, one barrier/chunk

// Weights pre-baked in PERMUTED mma B-fragment layout, fp16 2-level split,
// scaled by 128 (exact power of 2; epilogue multiplies by 1/128).
// u16 idx = (((chunk*4+ks)*4+nt)*32+lane)*8 + level*4 + reg*2 + half
__device__ uint16_t g_wfrag[NCHUNK * 4 * 4 * 32 * 8];   // 128 KB
__device__ float    g_biasC[NOUT];

// ---------------------------------------------------------------------------
__device__ __forceinline__ uint32_t smem_u32(const void* p) {
    uint32_t a;
    asm("{ .reg .u64 t; cvta.to.shared.u64 t, %1; cvt.u32.u64 %0, t; }"
        : "=r"(a) : "l"(p));
    return a;
}
__device__ __forceinline__ void cpa16(uint32_t saddr, const void* g) {
    asm volatile("cp.async.cg.shared.global [%0], [%1], 16;" :: "r"(saddr), "l"(g));
}
#define CP_COMMIT() asm volatile("cp.async.commit_group;" ::: "memory")
#define CP_WAIT2()  asm volatile("cp.async.wait_group 2;"  ::: "memory")
#define CP_WAIT0()  asm volatile("cp.async.wait_group 0;"  ::: "memory")

// pack two fp32 -> f16x2 (lo -> low half, hi -> high half)
__device__ __forceinline__ uint32_t pack_f16x2(float hi, float lo) {
    uint32_t r;
    asm("cvt.rn.f16x2.f32 %0, %1, %2;" : "=r"(r) : "f"(hi), "f"(lo));
    return r;
}
__device__ __forceinline__ float lo_f16_as_f32(uint32_t h2) {
    float f;
    asm("{ .reg .b16 a, b; mov.b32 {a, b}, %1; cvt.f32.f16 %0, a; }" : "=f"(f) : "r"(h2));
    return f;
}
__device__ __forceinline__ float hi_f16_as_f32(uint32_t h2) {
    float f;
    asm("{ .reg .b16 a, b; mov.b32 {a, b}, %1; cvt.f32.f16 %0, b; }" : "=f"(f) : "r"(h2));
    return f;
}
#define LDS128(r, addr) \
    asm volatile("ld.shared.v4.b32 {%0,%1,%2,%3}, [%4];" \
        : "=r"((r)[0]), "=r"((r)[1]), "=r"((r)[2]), "=r"((r)[3]) : "r"(addr))
#define MMA_F16(c, a0, a1, a2, a3, b0, b1) \
    asm volatile("mma.sync.aligned.m16n8k16.row.col.f32.f16.f16.f32 " \
        "{%0,%1,%2,%3}, {%4,%5,%6,%7}, {%8,%9}, {%0,%1,%2,%3};" \
        : "+f"((c)[0]), "+f"((c)[1]), "+f"((c)[2]), "+f"((c)[3]) \
        : "r"(a0), "r"(a1), "r"(a2), "r"(a3), "r"(b0), "r"(b1))

// Compensated accumulate: (s,e) += a*b, error ~2^-45 relative
__device__ __forceinline__ void acc2(float& s, float& e, float a, float b) {
    float p    = a * b;
    float perr = fmaf(a, b, -p);          // exact product error
    float t    = s + p;                   // Knuth 2Sum (branch-free)
    float z    = t - s;
    float serr = (s - (t - z)) + (p - z);
    s = t;
    e += serr + perr;
}

// ---------------------------------------------------------------------------
// Pre-kernel (single): blocks 0..127 bake weights; block 128 computes biases.
// Weights: fp32-compensated combine -> x128 scale -> fp16 2-level split ->
// permuted B-fragment layout (frag-k f = reg*8+tig*2+half <-> ko = tig*4+
// reg*2+half so A frags come from float4 loads).
// ---------------------------------------------------------------------------
__global__ void build_combined(const float* __restrict__ W_proj,
                               const float* __restrict__ b_proj,
                               const float* __restrict__ W_route,
                               const float* __restrict__ b_route,
                               const float* __restrict__ W_noise,
                               const float* __restrict__ b_noise) {
    if (blockIdx.x == 128) {
        // ---- bias block: 8 threads per output ----
        int o   = threadIdx.x >> 3;    // 0..31
        int sub = threadIdx.x & 7;     // 0..7
        int p   = o & 15;
        const float* Wsel = (o < 16) ? W_route : W_noise;
        float s = 0.f, e = 0.f;
        #pragma unroll
        for (int i = 0; i < 32; i++) {
            int d = sub + i * 8;
            acc2(s, e, Wsel[p * 256 + d], b_proj[d]);
        }
        double v = (double)s + (double)e;
        #pragma unroll
        for (int off = 4; off; off >>= 1)
            v += __shfl_down_sync(0xffffffffu, v, off, 8);
        if (sub == 0) {
            float bsel = (o < 16) ? b_route[p] : b_noise[p];
            g_biasC[o] = (float)((double)bsel + v);
        }
        return;
    }

    int idx = blockIdx.x * blockDim.x + threadIdx.x;   // 0..32767
    int o = idx >> 10;          // 0..31 (uniform per warp)
    int k = idx & 1023;         // lane-fast -> coalesced W_proj
    int p = o & 15;
    const float* Wsel = (o < 16) ? W_route : W_noise;

    float val;
    if (k < 768) {
        float s0 = 0.f, e0 = 0.f, s1 = 0.f, e1 = 0.f;
        #pragma unroll 8
        for (int d = 0; d < 256; d += 2) {
            acc2(s0, e0, Wsel[p * 256 + d],     W_proj[(d) * 768 + k]);
            acc2(s1, e1, Wsel[p * 256 + d + 1], W_proj[(d + 1) * 768 + k]);
        }
        val = (float)(((double)s0 + (double)s1) + ((double)e0 + (double)e1));
    } else {
        val = 0.1f * Wsel[p * 256 + (k - 768)];
    }

    float sv = val * 128.0f;                 // exact scaling, keeps lo normal
    __half h = __float2half_rn(sv);
    __half l = __float2half_rn(sv - __half2float(h));

    int chunk = k >> 6, ks = (k >> 4) & 3, ko = k & 15;
    int tig = ko >> 2, reg = (ko >> 1) & 1, half = ko & 1;
    int nt = o >> 3, n = o & 7;
    int lane = n * 4 + tig;
    int base = (((chunk * 4 + ks) * 4 + nt) * 32 + lane) * 8 + reg * 2 + half;
    g_wfrag[base]     = __half_as_ushort(h);   // level 0 (hi)
    g_wfrag[base + 4] = __half_as_ushort(l);   // level 1 (lo)
}

// ---------------------------------------------------------------------------
// Main kernel: emulated-fp32 GEMM [128,1024]x[1024,32] via fp16 2-split on
// mma.sync.m16n8k16 (3 MMAs per tile). A loaded gmem->registers in fragment
// layout at HALF-CHUNK granularity with 4 rotating buffers (prefetch distance
// 3 half-chunks ~600+cyc to cover DRAM latency). B quad-buffered in smem via
// cp.async at distance 2 -> ONE barrier/chunk. Warp tile: 16 rows x 32 outs.
// ---------------------------------------------------------------------------
__global__ __launch_bounds__(256) void router_mma2(
    const float* __restrict__ z_n,     const float* __restrict__ z_sea,
    const float* __restrict__ z_trend, const float* __restrict__ noise_z,
    const float* __restrict__ noise_r, const int* __restrict__ patch_cand,
    float* __restrict__ out)
{
    extern __shared__ char dsm[];
    const uint32_t BS = smem_u32(dsm);          // NBUF x 8192 B (B fragments)
    float (*res)[33] = (float(*)[33])(dsm + NBUF * BCHUNK);   // 128 x 33 fp32

    const int tid  = threadIdx.x;
    const int wid  = tid >> 5;
    const int lane = tid & 31;
    const int row0 = blockIdx.x * MTILE;
    const int gid  = lane >> 2, tig = lane & 3;
    const int rA   = row0 + wid * 16 + gid;     // global row for a0/a2

    // A half-chunk loader: h = 0..31; chunk c = h>>1, half = h&1 (2 ks steps)
    auto lda_half = [&](float4* r, int h) {
        int c = h >> 1;
        const float* src = (c < 8) ? ((c < 4) ? z_n : z_sea)
                                   : ((c < 12) ? z_trend : noise_z);
        const float* p0 = src + (size_t)rA * DIM + (c & 3) * 64
                              + (h & 1) * 32 + tig * 4;
        r[0] = __ldg((const float4*)(p0));
        r[1] = __ldg((const float4*)(p0 + 8 * DIM));
        r[2] = __ldg((const float4*)(p0 + 16));
        r[3] = __ldg((const float4*)(p0 + 16 + 8 * DIM));
    };
    auto stageB = [&](int c) {
        uint32_t dst = BS + (c % NBUF) * BCHUNK + tid * 32;
        const char* src = (const char*)g_wfrag + (size_t)c * BCHUNK + tid * 32;
        cpa16(dst, src);
        cpa16(dst + 16, src + 16);
        CP_COMMIT();
    };

    float acc0[4][4], acc1[4][4];
    #pragma unroll
    for (int nt = 0; nt < 4; nt++)
        #pragma unroll
        for (int i = 0; i < 4; i++) { acc0[nt][i] = 0.f; acc1[nt][i] = 0.f; }

    // one ks step (16 K) against B chunk base bb
    auto do_ks = [&](float4 v0, float4 v1, uint32_t bb, int ks) {
        uint32_t h0 = pack_f16x2(v0.y, v0.x);
        uint32_t h1 = pack_f16x2(v1.y, v1.x);
        uint32_t h2 = pack_f16x2(v0.w, v0.z);
        uint32_t h3 = pack_f16x2(v1.w, v1.z);
        uint32_t l0 = pack_f16x2(v0.y - hi_f16_as_f32(h0), v0.x - lo_f16_as_f32(h0));
        uint32_t l1 = pack_f16x2(v1.y - hi_f16_as_f32(h1), v1.x - lo_f16_as_f32(h1));
        uint32_t l2 = pack_f16x2(v0.w - hi_f16_as_f32(h2), v0.z - lo_f16_as_f32(h2));
        uint32_t l3 = pack_f16x2(v1.w - hi_f16_as_f32(h3), v1.z - lo_f16_as_f32(h3));
        #pragma unroll
        for (int nt = 0; nt < 4; nt++) {
            uint32_t b[4];
            LDS128(b, bb + (uint32_t)(((ks * 4 + nt) * 32 + lane) * 16));
            MMA_F16(acc0[nt], h0, h1, h2, h3, b[0], b[1]);  // hi*hi
            MMA_F16(acc1[nt], h0, h1, h2, h3, b[2], b[3]);  // hi*lo
            MMA_F16(acc1[nt], l0, l1, l2, l3, b[0], b[1]);  // lo*hi
        }
    };

    float4 rb[4][4];
    lda_half(rb[0], 0);
    lda_half(rb[1], 1);
    lda_half(rb[2], 2);
    stageB(0);          // group 0
    stageB(1);          // group 1

    #pragma unroll 1
    for (int g = 0; g < 8; g++) {
        const int c0 = 2 * g, c1 = 2 * g + 1;
        const int h  = 4 * g;

        // slot h (chunk c0, half 0)
        if (h + 3 < 32) lda_half(rb[3], h + 3);
        if (c0 + 2 < NCHUNK) { stageB(c0 + 2); CP_WAIT2(); }
        else                 { CP_WAIT0(); }
        __syncthreads();
        const uint32_t bb0 = BS + (c0 % NBUF) * BCHUNK;
        do_ks(rb[0][0], rb[0][1], bb0, 0);
        do_ks(rb[0][2], rb[0][3], bb0, 1);

        // slot h+1 (chunk c0, half 1)
        if (h + 4 < 32) lda_half(rb[0], h + 4);
        do_ks(rb[1][0], rb[1][1], bb0, 2);
        do_ks(rb[1][2], rb[1][3], bb0, 3);

        // slot h+2 (chunk c1, half 0)
        if (h + 5 < 32) lda_half(rb[1], h + 5);
        if (c1 + 2 < NCHUNK) { stageB(c1 + 2); CP_WAIT2(); }
        else                 { CP_WAIT0(); }
        __syncthreads();
        const uint32_t bb1 = BS + (c1 % NBUF) * BCHUNK;
        do_ks(rb[2][0], rb[2][1], bb1, 0);
        do_ks(rb[2][2], rb[2][3], bb1, 1);

        // slot h+3 (chunk c1, half 1)
        if (h + 6 < 32) lda_half(rb[2], h + 6);
        do_ks(rb[3][0], rb[3][1], bb1, 2);
        do_ks(rb[3][2], rb[3][3], bb1, 3);
    }

    // ---- stash per-row results (undo x128 weight scale) ----
    #pragma unroll
    for (int nt = 0; nt < 4; nt++) {
        int cb = nt * 8 + tig * 2;
        int r  = wid * 16 + gid;
        res[r][cb]         = (acc0[nt][0] + acc1[nt][0]) * 0.0078125f;
        res[r][cb + 1]     = (acc0[nt][1] + acc1[nt][1]) * 0.0078125f;
        res[r + 8][cb]     = (acc0[nt][2] + acc1[nt][2]) * 0.0078125f;
        res[r + 8][cb + 1] = (acc0[nt][3] + acc1[nt][3]) * 0.0078125f;
    }
    __syncthreads();

    // ---- epilogue: one thread per row (threads 0..127) ----
    if (tid < MTILE) {
        const int grow = row0 + tid;
        float v[32];
        #pragma unroll
        for (int o = 0; o < 32; o++) v[o] = res[tid][o];

        float nr[16];
        #pragma unroll
        for (int i = 0; i < 4; i++) {
            float4 t = __ldg((const float4*)(noise_r + (size_t)grow * 16 + i * 4));
            nr[i*4+0] = t.x; nr[i*4+1] = t.y; nr[i*4+2] = t.z; nr[i*4+3] = t.w;
        }

        float logit[16];
        #pragma unroll
        for (int p = 0; p < 16; p++) {
            float pre = v[16 + p] + g_biasC[16 + p];
            float sp  = fmaxf(pre, 0.0f) + log1pf(expf(-fabsf(pre)));
            logit[p]  = v[p] + g_biasC[p] + nr[p] * sp;
        }
        float m = logit[0];
        #pragma unroll
        for (int p = 1; p < 16; p++) m = fmaxf(m, logit[p]);
        float e[16], s = 0.0f;
        #pragma unroll
        for (int p = 0; p < 16; p++) { e[p] = expf(logit[p] - m); s += e[p]; }
        float w[16];
        #pragma unroll
        for (int p = 0; p < 16; p++) w[p] = e[p] / s;

        float sp_out[16];
        #pragma unroll
        for (int p = 0; p < 16; p++) sp_out[p] = 0.0f;
        int idxs[4];
        unsigned mask = 0u;
        #pragma unroll
        for (int kk = 0; kk < 4; kk++) {
            float best = -1.0f; int bi = 0;
            #pragma unroll
            for (int p = 0; p < 16; p++) {
                bool fr = ((mask >> p) & 1u) == 0u;
                if (fr && w[p] > best) { best = w[p]; bi = p; }
            }
            mask |= 1u << bi;
            idxs[kk] = bi;
            sp_out[bi] = best;
        }

        float* sp_ptr = out + (size_t)grow * 16;
        #pragma unroll
        for (int i = 0; i < 4; i++)
            *(float4*)(sp_ptr + i * 4) = make_float4(sp_out[i*4+0], sp_out[i*4+1],
                                                     sp_out[i*4+2], sp_out[i*4+3]);
        float* pp = out + (size_t)BATCH * 16 + (size_t)grow * 4;
        float* ip = out + (size_t)BATCH * 20 + (size_t)grow * 4;
        #pragma unroll
        for (int kk = 0; kk < 4; kk++) {
            pp[kk] = (float)__ldg(patch_cand + idxs[kk]);
            ip[kk] = (float)idxs[kk];
        }
    }
}

// ---------------------------------------------------------------------------
extern "C" void kernel_launch(void* const* d_in, const int* in_sizes, int n_in,
                              void* d_out, int out_size) {
    const float* z_n        = (const float*)d_in[0];
    const float* z_sea      = (const float*)d_in[1];
    const float* z_trend    = (const float*)d_in[2];
    const float* noise_z    = (const float*)d_in[3];
    const float* noise_r    = (const float*)d_in[4];
    const int*   patch_cand = (const int*)  d_in[5];
    const float* W_proj     = (const float*)d_in[6];
    const float* b_proj     = (const float*)d_in[7];
    const float* W_route    = (const float*)d_in[8];
    const float* b_route    = (const float*)d_in[9];
    const float* W_noise    = (const float*)d_in[10];
    const float* b_noise    = (const float*)d_in[11];
    float* out = (float*)d_out;

    const int smem_bytes = NBUF * BCHUNK + 128 * 33 * 4;   // 32768 + 16896 = 49664
    static bool attr_set = false;
    if (!attr_set) {
        cudaFuncSetAttribute(router_mma2,
                             cudaFuncAttributeMaxDynamicSharedMemorySize,
                             smem_bytes);
        attr_set = true;
    }

    build_combined<<<129, 256>>>(W_proj, b_proj, W_route, b_route,
                                 W_noise, b_noise);

    router_mma2<<<BATCH / MTILE, 256, smem_bytes>>>(
        z_n, z_sea, z_trend, noise_z, noise_r, patch_cand, out);
}

// round 16
// speedup vs baseline: 1.3646x; 1.3646x over previous
#include <cuda_runtime.h>
#include <cuda_fp16.h>
#include <cstdint>
#include <math.h>

#define BATCH   131072
#define DIM     256
#define KTOT    1024
#define NOUT    32
#define MTILE   128      // rows per block
#define NCHUNK  16
#define BCHUNK  8192     // B-fragment bytes per chunk: 4ks x 4nt x 32lane x 16B
#define NBUF    4        // B smem buffers; prefetch distance 2, one barrier/chunk

// Weights pre-baked in PERMUTED mma B-fragment layout, fp16 2-level split,
// scaled by 128 (exact power of 2; epilogue multiplies by 1/128).
// u16 idx = (((chunk*4+ks)*4+nt)*32+lane)*8 + level*4 + reg*2 + half
__device__ uint16_t g_wfrag[NCHUNK * 4 * 4 * 32 * 8];   // 128 KB
__device__ float    g_biasC[NOUT];

// ---------------------------------------------------------------------------
__device__ __forceinline__ uint32_t smem_u32(const void* p) {
    uint32_t a;
    asm("{ .reg .u64 t; cvta.to.shared.u64 t, %1; cvt.u32.u64 %0, t; }"
        : "=r"(a) : "l"(p));
    return a;
}
__device__ __forceinline__ void cpa16(uint32_t saddr, const void* g) {
    asm volatile("cp.async.cg.shared.global [%0], [%1], 16;" :: "r"(saddr), "l"(g));
}
#define CP_COMMIT() asm volatile("cp.async.commit_group;" ::: "memory")
#define CP_WAIT2()  asm volatile("cp.async.wait_group 2;"  ::: "memory")
#define CP_WAIT0()  asm volatile("cp.async.wait_group 0;"  ::: "memory")

// pack two fp32 -> f16x2 (lo -> low half, hi -> high half)
__device__ __forceinline__ uint32_t pack_f16x2(float hi, float lo) {
    uint32_t r;
    asm("cvt.rn.f16x2.f32 %0, %1, %2;" : "=r"(r) : "f"(hi), "f"(lo));
    return r;
}
__device__ __forceinline__ float lo_f16_as_f32(uint32_t h2) {
    float f;
    asm("{ .reg .b16 a, b; mov.b32 {a, b}, %1; cvt.f32.f16 %0, a; }" : "=f"(f) : "r"(h2));
    return f;
}
__device__ __forceinline__ float hi_f16_as_f32(uint32_t h2) {
    float f;
    asm("{ .reg .b16 a, b; mov.b32 {a, b}, %1; cvt.f32.f16 %0, b; }" : "=f"(f) : "r"(h2));
    return f;
}
#define LDS128(r, addr) \
    asm volatile("ld.shared.v4.b32 {%0,%1,%2,%3}, [%4];" \
        : "=r"((r)[0]), "=r"((r)[1]), "=r"((r)[2]), "=r"((r)[3]) : "r"(addr))
#define MMA_F16(c, a0, a1, a2, a3, b0, b1) \
    asm volatile("mma.sync.aligned.m16n8k16.row.col.f32.f16.f16.f32 " \
        "{%0,%1,%2,%3}, {%4,%5,%6,%7}, {%8,%9}, {%0,%1,%2,%3};" \
        : "+f"((c)[0]), "+f"((c)[1]), "+f"((c)[2]), "+f"((c)[3]) \
        : "r"(a0), "r"(a1), "r"(a2), "r"(a3), "r"(b0), "r"(b1))

// Compensated accumulate: (s,e) += a*b, error ~2^-45 relative
__device__ __forceinline__ void acc2(float& s, float& e, float a, float b) {
    float p    = a * b;
    float perr = fmaf(a, b, -p);          // exact product error
    float t    = s + p;                   // Knuth 2Sum (branch-free)
    float z    = t - s;
    float serr = (s - (t - z)) + (p - z);
    s = t;
    e += serr + perr;
}

// ---------------------------------------------------------------------------
// Pre-kernel (single): blocks 0..127 bake weights; block 128 computes biases.
// Weights: fp32-compensated combine -> x128 scale -> fp16 2-level split ->
// permuted B-fragment layout (frag-k f = reg*8+tig*2+half <-> ko = tig*4+
// reg*2+half so A frags come from float4 loads).
// ---------------------------------------------------------------------------
__global__ void build_combined(const float* __restrict__ W_proj,
                               const float* __restrict__ b_proj,
                               const float* __restrict__ W_route,
                               const float* __restrict__ b_route,
                               const float* __restrict__ W_noise,
                               const float* __restrict__ b_noise) {
    if (blockIdx.x == 128) {
        // ---- bias block: 8 threads per output ----
        int o   = threadIdx.x >> 3;    // 0..31
        int sub = threadIdx.x & 7;     // 0..7
        int p   = o & 15;
        const float* Wsel = (o < 16) ? W_route : W_noise;
        float s = 0.f, e = 0.f;
        #pragma unroll
        for (int i = 0; i < 32; i++) {
            int d = sub + i * 8;
            acc2(s, e, Wsel[p * 256 + d], b_proj[d]);
        }
        double v = (double)s + (double)e;
        #pragma unroll
        for (int off = 4; off; off >>= 1)
            v += __shfl_down_sync(0xffffffffu, v, off, 8);
        if (sub == 0) {
            float bsel = (o < 16) ? b_route[p] : b_noise[p];
            g_biasC[o] = (float)((double)bsel + v);
        }
        return;
    }

    int idx = blockIdx.x * blockDim.x + threadIdx.x;   // 0..32767
    int o = idx >> 10;          // 0..31 (uniform per warp)
    int k = idx & 1023;         // lane-fast -> coalesced W_proj
    int p = o & 15;
    const float* Wsel = (o < 16) ? W_route : W_noise;

    float val;
    if (k < 768) {
        float s0 = 0.f, e0 = 0.f, s1 = 0.f, e1 = 0.f;
        #pragma unroll 8
        for (int d = 0; d < 256; d += 2) {
            acc2(s0, e0, Wsel[p * 256 + d],     W_proj[(d) * 768 + k]);
            acc2(s1, e1, Wsel[p * 256 + d + 1], W_proj[(d + 1) * 768 + k]);
        }
        val = (float)(((double)s0 + (double)s1) + ((double)e0 + (double)e1));
    } else {
        val = 0.1f * Wsel[p * 256 + (k - 768)];
    }

    float sv = val * 128.0f;                 // exact scaling, keeps lo normal
    __half h = __float2half_rn(sv);
    __half l = __float2half_rn(sv - __half2float(h));

    int chunk = k >> 6, ks = (k >> 4) & 3, ko = k & 15;
    int tig = ko >> 2, reg = (ko >> 1) & 1, half = ko & 1;
    int nt = o >> 3, n = o & 7;
    int lane = n * 4 + tig;
    int base = (((chunk * 4 + ks) * 4 + nt) * 32 + lane) * 8 + reg * 2 + half;
    g_wfrag[base]     = __half_as_ushort(h);   // level 0 (hi)
    g_wfrag[base + 4] = __half_as_ushort(l);   // level 1 (lo)
}

// ---------------------------------------------------------------------------
// Main kernel (R12/R14 structure — best known, 126 regs / 2 blocks/SM):
// emulated-fp32 GEMM [128,1024]x[1024,32] via fp16 2-split on
// mma.sync.m16n8k16 (3 MMAs per tile). A loaded gmem->registers in fragment
// layout (permuted k, double-buffered per chunk). B quad-buffered in smem via
// cp.async at prefetch distance 2 -> ONE barrier per chunk. Warp tile:
// 16 rows x 32 outs. 8 warps. Fused softplus/noise/softmax/top4 epilogue.
// ---------------------------------------------------------------------------
__global__ __launch_bounds__(256) void router_mma2(
    const float* __restrict__ z_n,     const float* __restrict__ z_sea,
    const float* __restrict__ z_trend, const float* __restrict__ noise_z,
    const float* __restrict__ noise_r, const int* __restrict__ patch_cand,
    float* __restrict__ out)
{
    extern __shared__ char dsm[];
    const uint32_t BS = smem_u32(dsm);          // NBUF x 8192 B (B fragments)
    float (*res)[33] = (float(*)[33])(dsm + NBUF * BCHUNK);   // 128 x 33 fp32

    const int tid  = threadIdx.x;
    const int wid  = tid >> 5;
    const int lane = tid & 31;
    const int row0 = blockIdx.x * MTILE;
    const int gid  = lane >> 2, tig = lane & 3;
    const int rA   = row0 + wid * 16 + gid;     // global row for a0/a2

    // A loader: per ks, float4 at (rA, colbase + ks*16 + tig*4) and (rA+8, ...)
    auto lda = [&](float4* r, int c) {
        const float* src = (c < 8) ? ((c < 4) ? z_n : z_sea)
                                   : ((c < 12) ? z_trend : noise_z);
        const float* p0 = src + (size_t)rA * DIM + (c & 3) * 64 + tig * 4;
        #pragma unroll
        for (int ks = 0; ks < 4; ks++) {
            r[2 * ks]     = __ldg((const float4*)(p0 + ks * 16));
            r[2 * ks + 1] = __ldg((const float4*)(p0 + 8 * DIM + ks * 16));
        }
    };
    auto stageB = [&](int c) {
        uint32_t dst = BS + (c % NBUF) * BCHUNK + tid * 32;
        const char* src = (const char*)g_wfrag + (size_t)c * BCHUNK + tid * 32;
        cpa16(dst, src);
        cpa16(dst + 16, src + 16);
        CP_COMMIT();
    };

    float acc0[4][4], acc1[4][4];
    #pragma unroll
    for (int nt = 0; nt < 4; nt++)
        #pragma unroll
        for (int i = 0; i < 4; i++) { acc0[nt][i] = 0.f; acc1[nt][i] = 0.f; }

    float4 rc[8], rn[8];
    stageB(0);          // group 0
    stageB(1);          // group 1
    lda(rc, 0);

    for (int c = 0; c < NCHUNK; c++) {
        if (c + 1 < NCHUNK) lda(rn, c + 1);
        if (c + 2 < NCHUNK) { stageB(c + 2); CP_WAIT2(); }  // group c landed
        else                { CP_WAIT0(); }
        __syncthreads();                        // single barrier per chunk

        const uint32_t bb = BS + (c % NBUF) * BCHUNK;
        #pragma unroll
        for (int ks = 0; ks < 4; ks++) {
            float4 v0 = rc[2 * ks], v1 = rc[2 * ks + 1];
            // hi level (frag regs: a0=v0.xy a1=v1.xy a2=v0.zw a3=v1.zw)
            uint32_t h0 = pack_f16x2(v0.y, v0.x);
            uint32_t h1 = pack_f16x2(v1.y, v1.x);
            uint32_t h2 = pack_f16x2(v0.w, v0.z);
            uint32_t h3 = pack_f16x2(v1.w, v1.z);
            // lo level = exact residual
            uint32_t l0 = pack_f16x2(v0.y - hi_f16_as_f32(h0), v0.x - lo_f16_as_f32(h0));
            uint32_t l1 = pack_f16x2(v1.y - hi_f16_as_f32(h1), v1.x - lo_f16_as_f32(h1));
            uint32_t l2 = pack_f16x2(v0.w - hi_f16_as_f32(h2), v0.z - lo_f16_as_f32(h2));
            uint32_t l3 = pack_f16x2(v1.w - hi_f16_as_f32(h3), v1.z - lo_f16_as_f32(h3));

            #pragma unroll
            for (int nt = 0; nt < 4; nt++) {
                uint32_t b[4];
                LDS128(b, bb + (uint32_t)(((ks * 4 + nt) * 32 + lane) * 16));
                MMA_F16(acc0[nt], h0, h1, h2, h3, b[0], b[1]);  // hi*hi
                MMA_F16(acc1[nt], h0, h1, h2, h3, b[2], b[3]);  // hi*lo
                MMA_F16(acc1[nt], l0, l1, l2, l3, b[0], b[1]);  // lo*hi
            }
        }
        #pragma unroll
        for (int g = 0; g < 8; g++) rc[g] = rn[g];
    }

    // ---- stash per-row results (undo x128 weight scale) ----
    #pragma unroll
    for (int nt = 0; nt < 4; nt++) {
        int cb = nt * 8 + tig * 2;
        int r  = wid * 16 + gid;
        res[r][cb]         = (acc0[nt][0] + acc1[nt][0]) * 0.0078125f;
        res[r][cb + 1]     = (acc0[nt][1] + acc1[nt][1]) * 0.0078125f;
        res[r + 8][cb]     = (acc0[nt][2] + acc1[nt][2]) * 0.0078125f;
        res[r + 8][cb + 1] = (acc0[nt][3] + acc1[nt][3]) * 0.0078125f;
    }
    __syncthreads();

    // ---- epilogue: one thread per row (threads 0..127) ----
    if (tid < MTILE) {
        const int grow = row0 + tid;
        float v[32];
        #pragma unroll
        for (int o = 0; o < 32; o++) v[o] = res[tid][o];

        float nr[16];
        #pragma unroll
        for (int i = 0; i < 4; i++) {
            float4 t = __ldg((const float4*)(noise_r + (size_t)grow * 16 + i * 4));
            nr[i*4+0] = t.x; nr[i*4+1] = t.y; nr[i*4+2] = t.z; nr[i*4+3] = t.w;
        }

        float logit[16];
        #pragma unroll
        for (int p = 0; p < 16; p++) {
            float pre = v[16 + p] + g_biasC[16 + p];
            float sp  = fmaxf(pre, 0.0f) + log1pf(expf(-fabsf(pre)));
            logit[p]  = v[p] + g_biasC[p] + nr[p] * sp;
        }
        float m = logit[0];
        #pragma unroll
        for (int p = 1; p < 16; p++) m = fmaxf(m, logit[p]);
        float e[16], s = 0.0f;
        #pragma unroll
        for (int p = 0; p < 16; p++) { e[p] = expf(logit[p] - m); s += e[p]; }
        float w[16];
        #pragma unroll
        for (int p = 0; p < 16; p++) w[p] = e[p] / s;

        float sp_out[16];
        #pragma unroll
        for (int p = 0; p < 16; p++) sp_out[p] = 0.0f;
        int idxs[4];
        unsigned mask = 0u;
        #pragma unroll
        for (int kk = 0; kk < 4; kk++) {
            float best = -1.0f; int bi = 0;
            #pragma unroll
            for (int p = 0; p < 16; p++) {
                bool fr = ((mask >> p) & 1u) == 0u;
                if (fr && w[p] > best) { best = w[p]; bi = p; }
            }
            mask |= 1u << bi;
            idxs[kk] = bi;
            sp_out[bi] = best;
        }

        float* sp_ptr = out + (size_t)grow * 16;
        #pragma unroll
        for (int i = 0; i < 4; i++)
            *(float4*)(sp_ptr + i * 4) = make_float4(sp_out[i*4+0], sp_out[i*4+1],
                                                     sp_out[i*4+2], sp_out[i*4+3]);
        float* pp = out + (size_t)BATCH * 16 + (size_t)grow * 4;
        float* ip = out + (size_t)BATCH * 20 + (size_t)grow * 4;
        #pragma unroll
        for (int kk = 0; kk < 4; kk++) {
            pp[kk] = (float)__ldg(patch_cand + idxs[kk]);
            ip[kk] = (float)idxs[kk];
        }
    }
}

// ---------------------------------------------------------------------------
extern "C" void kernel_launch(void* const* d_in, const int* in_sizes, int n_in,
                              void* d_out, int out_size) {
    const float* z_n        = (const float*)d_in[0];
    const float* z_sea      = (const float*)d_in[1];
    const float* z_trend    = (const float*)d_in[2];
    const float* noise_z    = (const float*)d_in[3];
    const float* noise_r    = (const float*)d_in[4];
    const int*   patch_cand = (const int*)  d_in[5];
    const float* W_proj     = (const float*)d_in[6];
    const float* b_proj     = (const float*)d_in[7];
    const float* W_route    = (const float*)d_in[8];
    const float* b_route    = (const float*)d_in[9];
    const float* W_noise    = (const float*)d_in[10];
    const float* b_noise    = (const float*)d_in[11];
    float* out = (float*)d_out;

    const int smem_bytes = NBUF * BCHUNK + 128 * 33 * 4;   // 32768 + 16896 = 49664
    static bool attr_set = false;
    if (!attr_set) {
        cudaFuncSetAttribute(router_mma2,
                             cudaFuncAttributeMaxDynamicSharedMemorySize,
                             smem_bytes);
        attr_set = true;
    }

    build_combined<<<129, 256>>>(W_proj, b_proj, W_route, b_route,
                                 W_noise, b_noise);

    router_mma2<<<BATCH / MTILE, 256, smem_bytes>>>(
        z_n, z_sea, z_trend, noise_z, noise_r, patch_cand, out);
}